// round 13
// baseline (speedup 1.0000x reference)
#include <cuda_runtime.h>
#include <cuda_bf16.h>
#include <cstdint>

// NeighborListForTraining: all intra-molecule ordered pairs (i!=j) for
// 2000 molecules x 64 atoms. Output (float32, concatenated flat):
//   [0,P) i_idx | [P,2P) j_idx | [2P,3P) d_ij | [3P,6P) r_ij[P][3]
// P = n_mols * 4032 = 8,064,000.
//
// R13 (= R12 retry; R12 hit broker infra failure, kernel never ran):
// In R8 the compiler narrows pj float4 reads to 3 scalar LDS with an 8-way
// bank conflict (lane jl-stride 2 slots -> 4 of 32 banks); LDS replays are
// ~69% of L1 cycles = the measured 73% ceiling that binds at occ 86%.
// Fix (R4's swizzle, now on the high-occupancy base): forced LDS.128 with
// XOR bank swizzle -> conflict-free pj loads. Everything else = R8.

#define NPM    64
#define PPM    4032          // pairs per molecule
#define HPP    2016          // pairs per half-molecule (one block)
#define HGR    1008          // groups of 2 pairs per block
#define CUTOFF 5.0f
#define BLOCK  256

// Swizzled slot for atom a: bank16(slot) = (a&7) ^ ((a>>3)&7).
// With lane-stride-2 atom access, each 8-lane LDS.128 phase-group hits all
// 8 distinct 16B banks -> conflict-free.
__device__ __forceinline__ int swz(int a) {
    return (a & ~7) | ((a ^ (a >> 3)) & 7);
}

// Forced 128-bit shared load — compiler cannot narrow this.
__device__ __forceinline__ float4 lds128(const float4* p) {
    float4 v;
    uint32_t a = (uint32_t)__cvta_generic_to_shared((void*)p);
    asm("ld.shared.v4.f32 {%0,%1,%2,%3}, [%4];"
        : "=f"(v.x), "=f"(v.y), "=f"(v.z), "=f"(v.w)
        : "r"(a));
    return v;
}

__device__ __forceinline__ void stcs2(float* p, float2 v) {
    __stcs((float2*)p, v);
}

__global__ __launch_bounds__(BLOCK, 8) void neighborlist_kernel(
    const float* __restrict__ pos,   // [n_atoms, 3]
    float* __restrict__ out,
    int n_mols)
{
    __shared__ float4 s_pos[NPM];

    const int mol  = blockIdx.x >> 1;
    const int half = blockIdx.x & 1;
    const float* mp = pos + (size_t)mol * (NPM * 3);

    if (threadIdx.x < NPM) {
        const int a = threadIdx.x;
        s_pos[swz(a)] = make_float4(mp[3 * a + 0], mp[3 * a + 1],
                                    mp[3 * a + 2], 0.0f);
    }
    __syncthreads();

    const long long P = (long long)n_mols * PPM;
    float* __restrict__ out_i = out;
    float* __restrict__ out_j = out + P;
    float* __restrict__ out_d = out + 2 * P;
    float* __restrict__ out_r = out + 3 * P;

    const float atom_basef = (float)(mol * NPM);
    const long long base_pair = (long long)mol * PPM + (long long)half * HPP;
    const int tlocal0 = half * HPP;

    for (int g = threadIdx.x; g < HGR; g += BLOCK) {
        const int t0 = tlocal0 + g * 2;

        float2 fi, fj, fd;
        float  rr[6];

        #pragma unroll
        for (int k = 0; k < 2; k++) {
            const int t  = t0 + k;             // 0..4031
            const int il = t / 63;
            const int rm = t - il * 63;
            const int jl = rm + (rm >= il);

            const float4 pi = lds128(&s_pos[swz(il)]);  // near-broadcast
            const float4 pj = lds128(&s_pos[swz(jl)]);  // conflict-free

            float dx = pj.x - pi.x;
            float dy = pj.y - pi.y;
            float dz = pj.z - pi.z;
            float d  = sqrtf(dx * dx + dy * dy + dz * dz);

            if (!(d <= CUTOFF)) { d = 0.0f; dx = 0.0f; dy = 0.0f; dz = 0.0f; }

            ((float*)&fi)[k] = atom_basef + (float)il;
            ((float*)&fj)[k] = atom_basef + (float)jl;
            ((float*)&fd)[k] = d;
            rr[3 * k + 0] = dx;
            rr[3 * k + 1] = dy;
            rr[3 * k + 2] = dz;
        }

        const long long p = base_pair + g * 2;   // p % 2 == 0 -> 8B aligned
        stcs2(out_i + p, fi);
        stcs2(out_j + p, fj);
        stcs2(out_d + p, fd);

        float* orr = out_r + 3 * p;              // 3p % 2 == 0 -> 8B aligned
        stcs2(orr + 0, make_float2(rr[0], rr[1]));
        stcs2(orr + 2, make_float2(rr[2], rr[3]));
        stcs2(orr + 4, make_float2(rr[4], rr[5]));
    }
}

extern "C" void kernel_launch(void* const* d_in, const int* in_sizes, int n_in,
                              void* d_out, int out_size)
{
    const float* positions = (const float*)d_in[0];
    const int n_atoms = in_sizes[0] / 3;
    const int n_mols  = n_atoms / NPM;

    float* out = (float*)d_out;
    neighborlist_kernel<<<n_mols * 2, BLOCK>>>(positions, out, n_mols);
}